// round 12
// baseline (speedup 1.0000x reference)
#include <cuda_runtime.h>

// ---------------------------------------------------------------------------
// GNN forward: 3 layers of COO SpMM (gather + scatter-add) + gating, mean out.
//   per layer: agg = A @ ego ; ego = agg + agg*ego ; acc += ego
//   out = acc / 4
// Node matrices (19.2 MB each) are L2-resident; scatter uses red.global.v4.f32.
// ---------------------------------------------------------------------------

namespace {
constexpr int NN  = 50000;     // nodes
constexpr int EE  = 800000;    // edges
constexpr int D   = 96;        // embedding dim
constexpr int D4  = D / 4;     // float4 per row = 24
constexpr int NV4 = NN * D4;   // 1.2M float4 elements per node matrix
constexpr int EPB = 16;        // edges per scatter block
constexpr int SCATTER_BLOCK = EPB * D4;  // 384 threads
}

// Scratch (allocation-free rule: __device__ globals only).
__device__ __align__(16) float g_ego[(size_t)NN * D];
__device__ __align__(16) float g_agg[(size_t)NN * D];
__device__ int g_idx64;  // 1 if rows/cols are int64, 0 if int32

// JAX silently downcasts int64->int32 when x64 is disabled; element counts
// can't disambiguate. Detect from data: int64 indices < 50000 have zero high
// words; random int32 indices at odd u32 positions are ~never all zero.
__global__ void detect_idx64_kernel(const unsigned int* __restrict__ rows_u32) {
    if (blockIdx.x == 0 && threadIdx.x == 0) {
        int is64 = 1;
        for (int i = 0; i < 64; i++) {
            if (rows_u32[2 * i + 1] != 0u) { is64 = 0; break; }
        }
        g_idx64 = is64;
    }
}

// acc(out) = X ; agg = 0  (agg also re-zeroed by update_kernel each layer,
// so replays stay clean; this covers the very first call path too).
__global__ void init_kernel(const float4* __restrict__ X, float4* __restrict__ out) {
    int i = blockIdx.x * blockDim.x + threadIdx.x;
    if (i < NV4) {
        out[i] = X[i];
        reinterpret_cast<float4*>(g_agg)[i] = make_float4(0.f, 0.f, 0.f, 0.f);
    }
}

__device__ __forceinline__ void red_add_v4(float4* p, float4 v) {
    asm volatile("red.global.add.v4.f32 [%0], {%1, %2, %3, %4};"
                 :: "l"(p), "f"(v.x), "f"(v.y), "f"(v.z), "f"(v.w)
                 : "memory");
}

// One edge per 24-thread group; each thread owns one float4 of the feature row.
__global__ __launch_bounds__(SCATTER_BLOCK)
void scatter_kernel(const float* __restrict__ Xsrc,
                    const float* __restrict__ vals,
                    const void*  __restrict__ rows_raw,
                    const void*  __restrict__ cols_raw,
                    int use_ego) {
    const int t    = threadIdx.x;
    const int grp  = t / D4;          // 0..15, edge group within block
    const int lane = t - grp * D4;    // 0..23, float4 slot within row
    const int e    = blockIdx.x * EPB + grp;
    if (e >= EE) return;

    long long r, c;
    if (g_idx64) {
        r = reinterpret_cast<const long long*>(rows_raw)[e];
        c = reinterpret_cast<const long long*>(cols_raw)[e];
    } else {
        r = reinterpret_cast<const int*>(rows_raw)[e];
        c = reinterpret_cast<const int*>(cols_raw)[e];
    }
    const float v = vals[e];

    const float4* src = use_ego ? reinterpret_cast<const float4*>(g_ego)
                                : reinterpret_cast<const float4*>(Xsrc);

    float4 m = src[(size_t)c * D4 + lane];
    m.x *= v; m.y *= v; m.z *= v; m.w *= v;

    red_add_v4(reinterpret_cast<float4*>(g_agg) + (size_t)r * D4 + lane, m);
}

// ego = agg + agg*ego ; acc += ego ; agg = 0 ; (last layer: acc *= 1/4)
__global__ void update_kernel(const float4* __restrict__ X,
                              float4* __restrict__ out,
                              int use_ego, int last) {
    int i = blockIdx.x * blockDim.x + threadIdx.x;
    if (i >= NV4) return;

    float4* agg = reinterpret_cast<float4*>(g_agg);
    float4* ego = reinterpret_cast<float4*>(g_ego);

    float4 a = agg[i];
    agg[i] = make_float4(0.f, 0.f, 0.f, 0.f);  // ready for next layer / replay

    float4 eo = use_ego ? ego[i] : X[i];

    float4 en;
    en.x = fmaf(a.x, eo.x, a.x);
    en.y = fmaf(a.y, eo.y, a.y);
    en.z = fmaf(a.z, eo.z, a.z);
    en.w = fmaf(a.w, eo.w, a.w);
    ego[i] = en;

    float4 acc = out[i];
    acc.x += en.x; acc.y += en.y; acc.z += en.z; acc.w += en.w;
    if (last) {
        acc.x *= 0.25f; acc.y *= 0.25f; acc.z *= 0.25f; acc.w *= 0.25f;
    }
    out[i] = acc;
}

extern "C" void kernel_launch(void* const* d_in, const int* in_sizes, int n_in,
                              void* d_out, int out_size) {
    const float* X    = (const float*)d_in[0];
    const float* vals = (const float*)d_in[1];
    const void*  rows = d_in[2];
    const void*  cols = d_in[3];
    float4* out = (float4*)d_out;

    (void)in_sizes; (void)n_in; (void)out_size;

    detect_idx64_kernel<<<1, 32>>>((const unsigned int*)rows);
    init_kernel<<<(NV4 + 255) / 256, 256>>>((const float4*)X, out);

    const int egrid = (EE + EPB - 1) / EPB;  // 50000 blocks
    for (int l = 0; l < 3; l++) {
        scatter_kernel<<<egrid, SCATTER_BLOCK>>>(X, vals, rows, cols, l > 0);
        update_kernel<<<(NV4 + 255) / 256, 256>>>((const float4*)X, out,
                                                  l > 0, l == 2);
    }
}

// round 13
// speedup vs baseline: 1.2392x; 1.2392x over previous
#include <cuda_runtime.h>

// ---------------------------------------------------------------------------
// GNN forward: 3 layers of COO SpMM (gather + scatter-add) + gating, mean out.
//   per layer: agg = A @ ego ; ego = agg + agg*ego ; acc += ego
//   out = acc / 4
// R12: ILP-4 update kernel, init fused into layer-1 update, layer-3 ego store
// dropped, templated layer variants. g_agg relies on static zero-init for the
// first call; every update re-zeroes it, so graph replays stay clean.
// ---------------------------------------------------------------------------

namespace {
constexpr int NN  = 50000;     // nodes
constexpr int EE  = 800000;    // edges
constexpr int D   = 96;        // embedding dim
constexpr int D4  = D / 4;     // float4 per row = 24
constexpr int NV4 = NN * D4;   // 1.2M float4 elements per node matrix
constexpr int EPB = 16;        // edges per scatter block
constexpr int SCATTER_BLOCK = EPB * D4;  // 384 threads
constexpr int UB = 256;        // update block
constexpr int UU = 4;          // update ILP factor (float4 per thread)
}

// Scratch (allocation-free rule: __device__ globals only). Zero-initialized
// at module load; g_agg is re-zeroed by every update_kernel invocation.
__device__ __align__(16) float g_ego[(size_t)NN * D];
__device__ __align__(16) float g_agg[(size_t)NN * D];
__device__ int g_idx64;  // 1 if rows/cols are int64, 0 if int32

// JAX silently downcasts int64->int32 when x64 is disabled; element counts
// can't disambiguate. Detect from data: int64 indices < 50000 have zero high
// words; random int32 indices at odd u32 positions are ~never all zero.
__global__ void detect_idx64_kernel(const unsigned int* __restrict__ rows_u32) {
    if (blockIdx.x == 0 && threadIdx.x == 0) {
        int is64 = 1;
        for (int i = 0; i < 64; i++) {
            if (rows_u32[2 * i + 1] != 0u) { is64 = 0; break; }
        }
        g_idx64 = is64;
    }
}

__device__ __forceinline__ void red_add_v4(float4* p, float4 v) {
    asm volatile("red.global.add.v4.f32 [%0], {%1, %2, %3, %4};"
                 :: "l"(p), "f"(v.x), "f"(v.y), "f"(v.z), "f"(v.w)
                 : "memory");
}

// One edge per 24-thread group; each thread owns one float4 of the feature row.
__global__ __launch_bounds__(SCATTER_BLOCK)
void scatter_kernel(const float* __restrict__ Xsrc,
                    const float* __restrict__ vals,
                    const void*  __restrict__ rows_raw,
                    const void*  __restrict__ cols_raw,
                    int use_ego) {
    const int t    = threadIdx.x;
    const int grp  = t / D4;          // 0..15, edge group within block
    const int lane = t - grp * D4;    // 0..23, float4 slot within row
    const int e    = blockIdx.x * EPB + grp;
    if (e >= EE) return;

    long long r, c;
    if (g_idx64) {
        r = reinterpret_cast<const long long*>(rows_raw)[e];
        c = reinterpret_cast<const long long*>(cols_raw)[e];
    } else {
        r = reinterpret_cast<const int*>(rows_raw)[e];
        c = reinterpret_cast<const int*>(cols_raw)[e];
    }
    const float v = vals[e];

    const float4* src = use_ego ? reinterpret_cast<const float4*>(g_ego)
                                : reinterpret_cast<const float4*>(Xsrc);

    float4 m = src[(size_t)c * D4 + lane];
    m.x *= v; m.y *= v; m.z *= v; m.w *= v;

    red_add_v4(reinterpret_cast<float4*>(g_agg) + (size_t)r * D4 + lane, m);
}

// MODE 0 (layer 1): ego_old = X,   out = X + en        (no out read)
// MODE 1 (layer 2): ego_old = ego, out += en
// MODE 2 (layer 3): ego_old = ego, out = (out + en)/4  (no ego store)
// All modes: en = agg + agg*ego_old ; agg = 0.
template<int MODE>
__global__ __launch_bounds__(UB)
void update_kernel(const float4* __restrict__ X, float4* __restrict__ out) {
    float4* agg = reinterpret_cast<float4*>(g_agg);
    float4* ego = reinterpret_cast<float4*>(g_ego);

    const int base = blockIdx.x * (UB * UU) + threadIdx.x;
    int  idx[UU];
    bool ok[UU];
#pragma unroll
    for (int k = 0; k < UU; k++) { idx[k] = base + k * UB; ok[k] = idx[k] < NV4; }

    float4 a[UU], e[UU], o[UU];
#pragma unroll
    for (int k = 0; k < UU; k++) if (ok[k]) a[k] = agg[idx[k]];
#pragma unroll
    for (int k = 0; k < UU; k++) if (ok[k])
        e[k] = (MODE == 0) ? __ldg(&X[idx[k]]) : ego[idx[k]];
    if (MODE != 0) {
#pragma unroll
        for (int k = 0; k < UU; k++) if (ok[k]) o[k] = out[idx[k]];
    }

#pragma unroll
    for (int k = 0; k < UU; k++) {
        if (!ok[k]) continue;
        float4 en;
        en.x = fmaf(a[k].x, e[k].x, a[k].x);
        en.y = fmaf(a[k].y, e[k].y, a[k].y);
        en.z = fmaf(a[k].z, e[k].z, a[k].z);
        en.w = fmaf(a[k].w, e[k].w, a[k].w);

        agg[idx[k]] = make_float4(0.f, 0.f, 0.f, 0.f);  // next layer / replay
        if (MODE != 2) ego[idx[k]] = en;

        float4 acc;
        if (MODE == 0) {
            acc.x = e[k].x + en.x; acc.y = e[k].y + en.y;
            acc.z = e[k].z + en.z; acc.w = e[k].w + en.w;
        } else {
            acc.x = o[k].x + en.x; acc.y = o[k].y + en.y;
            acc.z = o[k].z + en.z; acc.w = o[k].w + en.w;
        }
        if (MODE == 2) {
            acc.x *= 0.25f; acc.y *= 0.25f; acc.z *= 0.25f; acc.w *= 0.25f;
        }
        out[idx[k]] = acc;
    }
}

extern "C" void kernel_launch(void* const* d_in, const int* in_sizes, int n_in,
                              void* d_out, int out_size) {
    const float* X    = (const float*)d_in[0];
    const float* vals = (const float*)d_in[1];
    const void*  rows = d_in[2];
    const void*  cols = d_in[3];
    float4* out = (float4*)d_out;

    (void)in_sizes; (void)n_in; (void)out_size;

    detect_idx64_kernel<<<1, 32>>>((const unsigned int*)rows);

    const int egrid = (EE + EPB - 1) / EPB;            // 50000 blocks
    const int ugrid = (NV4 + UB * UU - 1) / (UB * UU); // 1172 blocks

    scatter_kernel<<<egrid, SCATTER_BLOCK>>>(X, vals, rows, cols, 0);
    update_kernel<0><<<ugrid, UB>>>((const float4*)X, out);

    scatter_kernel<<<egrid, SCATTER_BLOCK>>>(X, vals, rows, cols, 1);
    update_kernel<1><<<ugrid, UB>>>((const float4*)X, out);

    scatter_kernel<<<egrid, SCATTER_BLOCK>>>(X, vals, rows, cols, 1);
    update_kernel<2><<<ugrid, UB>>>((const float4*)X, out);
}

// round 14
// speedup vs baseline: 1.6078x; 1.2975x over previous
#include <cuda_runtime.h>

// ---------------------------------------------------------------------------
// GNN forward: 3 layers of COO SpMM + gating, mean over layers.
// R13: build CSR on device once per call (hist -> scan -> permute), then each
// layer is a fused warp-per-node SpMM + gating + acc epilogue. No atomics on
// feature data, no separate update kernel, ego double-buffered (A/B).
// ---------------------------------------------------------------------------

namespace {
constexpr int NN  = 50000;     // nodes
constexpr int EE  = 800000;    // edges
constexpr int D   = 96;        // embedding dim
constexpr int SCAN_T = 1024;
constexpr int CH = (NN + SCAN_T - 1) / SCAN_T;   // 49 rows per scan thread
}

// Scratch (allocation-free rule: __device__ globals only).
__device__ __align__(16) float g_bufA[(size_t)NN * D];
__device__ __align__(16) float g_bufB[(size_t)NN * D];
__device__ int   g_row_ptr[NN + 1];
__device__ int   g_fill[NN];          // counts, then fill cursors
__device__ int   g_ecol[EE];
__device__ float g_eval[EE];
__device__ int   g_idx64;             // 1 if rows/cols are int64, 0 if int32

// JAX silently downcasts int64->int32 when x64 is disabled; element counts
// can't disambiguate. Detect from data: int64 indices < 50000 have zero high
// words; random int32 indices at odd u32 positions are ~never all zero.
__global__ void detect_idx64_kernel(const unsigned int* __restrict__ rows_u32) {
    if (blockIdx.x == 0 && threadIdx.x == 0) {
        int is64 = 1;
        for (int i = 0; i < 64; i++) {
            if (rows_u32[2 * i + 1] != 0u) { is64 = 0; break; }
        }
        g_idx64 = is64;
    }
}

__global__ void zero_counts_kernel() {
    int i = blockIdx.x * blockDim.x + threadIdx.x;
    if (i < NN) g_fill[i] = 0;
}

__device__ __forceinline__ int load_idx(const void* p, int e) {
    return g_idx64 ? (int)reinterpret_cast<const long long*>(p)[e]
                   : reinterpret_cast<const int*>(p)[e];
}

__global__ void hist_kernel(const void* __restrict__ rows_raw) {
    int e = blockIdx.x * blockDim.x + threadIdx.x;
    if (e < EE) atomicAdd(&g_fill[load_idx(rows_raw, e)], 1);
}

// Single-block exclusive scan of g_fill -> g_row_ptr; also seeds g_fill with
// the fill cursors for the permute pass.
__global__ __launch_bounds__(SCAN_T)
void scan_kernel() {
    __shared__ int sh[SCAN_T];
    const int t = threadIdx.x;
    const int begin = t * CH;
    const int end = begin + CH < NN ? begin + CH : NN;

    int s = 0;
    for (int i = begin; i < end; i++) s += g_fill[i];
    sh[t] = s;
    __syncthreads();
    for (int off = 1; off < SCAN_T; off <<= 1) {   // Hillis-Steele inclusive
        int v = (t >= off) ? sh[t - off] : 0;
        __syncthreads();
        if (t >= off) sh[t] += v;
        __syncthreads();
    }
    int run = (t == 0) ? 0 : sh[t - 1];
    for (int i = begin; i < end; i++) {
        int cnt = g_fill[i];
        g_row_ptr[i] = run;
        g_fill[i] = run;       // fill cursor
        run += cnt;
    }
    if (t == SCAN_T - 1) g_row_ptr[NN] = sh[SCAN_T - 1];
}

__global__ void permute_kernel(const void* __restrict__ rows_raw,
                               const void* __restrict__ cols_raw,
                               const float* __restrict__ vals) {
    int e = blockIdx.x * blockDim.x + threadIdx.x;
    if (e >= EE) return;
    int r = load_idx(rows_raw, e);
    int c = load_idx(cols_raw, e);
    int pos = atomicAdd(&g_fill[r], 1);
    g_ecol[pos] = c;
    g_eval[pos] = vals[e];
}

// One warp per node. Lane l accumulates dims {l, l+32, l+64}.
// MODE 0: src = X,    dst = bufA, out = src_row + en
// MODE 1: src = bufA, dst = bufB, out += en
// MODE 2: src = bufB, no dst,     out = (out + en) * 0.25
template<int MODE>
__global__ __launch_bounds__(256)
void layer_kernel(const float* __restrict__ X, float* __restrict__ out) {
    const int node = (blockIdx.x * blockDim.x + threadIdx.x) >> 5;
    const int lane = threadIdx.x & 31;
    if (node >= NN) return;

    const float* __restrict__ src =
        (MODE == 0) ? X : (MODE == 1 ? g_bufA : g_bufB);
    float* __restrict__ dst = (MODE == 0) ? g_bufA : g_bufB;

    const int start = g_row_ptr[node];
    const int end   = g_row_ptr[node + 1];

    float a0 = 0.f, a1 = 0.f, a2 = 0.f;
    for (int b = start; b < end; b += 32) {
        const int nb = end - b < 32 ? end - b : 32;
        int   ce = 0;
        float ve = 0.f;
        if (lane < nb) { ce = g_ecol[b + lane]; ve = g_eval[b + lane]; }
        for (int j = 0; j < nb; j++) {
            const int   c = __shfl_sync(0xffffffffu, ce, j);
            const float v = __shfl_sync(0xffffffffu, ve, j);
            const float* __restrict__ row = src + (size_t)c * D;
            a0 = fmaf(v, __ldg(row + lane),      a0);
            a1 = fmaf(v, __ldg(row + lane + 32), a1);
            a2 = fmaf(v, __ldg(row + lane + 64), a2);
        }
    }

    const float* __restrict__ my = src + (size_t)node * D;
    const float e0 = my[lane], e1 = my[lane + 32], e2 = my[lane + 64];
    const float n0 = fmaf(a0, e0, a0);
    const float n1 = fmaf(a1, e1, a1);
    const float n2 = fmaf(a2, e2, a2);

    const size_t o = (size_t)node * D;
    if (MODE != 2) {
        dst[o + lane] = n0; dst[o + lane + 32] = n1; dst[o + lane + 64] = n2;
    }
    float o0, o1, o2;
    if (MODE == 0) {
        o0 = e0 + n0; o1 = e1 + n1; o2 = e2 + n2;        // acc = X + ego1
    } else {
        o0 = out[o + lane] + n0;
        o1 = out[o + lane + 32] + n1;
        o2 = out[o + lane + 64] + n2;
    }
    if (MODE == 2) { o0 *= 0.25f; o1 *= 0.25f; o2 *= 0.25f; }
    out[o + lane] = o0; out[o + lane + 32] = o1; out[o + lane + 64] = o2;
}

extern "C" void kernel_launch(void* const* d_in, const int* in_sizes, int n_in,
                              void* d_out, int out_size) {
    const float* X    = (const float*)d_in[0];
    const float* vals = (const float*)d_in[1];
    const void*  rows = d_in[2];
    const void*  cols = d_in[3];
    float* out = (float*)d_out;

    (void)in_sizes; (void)n_in; (void)out_size;

    detect_idx64_kernel<<<1, 32>>>((const unsigned int*)rows);

    // CSR build (once per call; reused by all 3 layers)
    zero_counts_kernel<<<(NN + 255) / 256, 256>>>();
    hist_kernel<<<(EE + 255) / 256, 256>>>(rows);
    scan_kernel<<<1, SCAN_T>>>();
    permute_kernel<<<(EE + 255) / 256, 256>>>(rows, cols, vals);

    const int lgrid = (NN * 32 + 255) / 256;   // one warp per node
    layer_kernel<0><<<lgrid, 256>>>(X, out);
    layer_kernel<1><<<lgrid, 256>>>(X, out);
    layer_kernel<2><<<lgrid, 256>>>(X, out);
}

// round 15
// speedup vs baseline: 2.4268x; 1.5094x over previous
#include <cuda_runtime.h>

// ---------------------------------------------------------------------------
// GNN forward: 3 layers of COO SpMM + gating, mean over layers.
// R14: replace the 70us single-block scan with a 3-phase parallel scan
// (block scans -> scan of block sums -> combine). CSR build + fused
// warp-per-node layer kernels otherwise unchanged from R13.
// ---------------------------------------------------------------------------

namespace {
constexpr int NN  = 50000;     // nodes
constexpr int EE  = 800000;    // edges
constexpr int D   = 96;        // embedding dim
constexpr int SB  = 256;                       // scan block
constexpr int NSB = (NN + SB - 1) / SB;        // 196 scan blocks
}

// Scratch (allocation-free rule: __device__ globals only).
__device__ __align__(16) float g_bufA[(size_t)NN * D];
__device__ __align__(16) float g_bufB[(size_t)NN * D];
__device__ int   g_row_ptr[NN + 1];
__device__ int   g_fill[NN];          // counts, then fill cursors
__device__ int   g_scan[NN];          // block-local inclusive scans
__device__ int   g_bsum[NSB];         // per-block sums -> exclusive offsets
__device__ int   g_ecol[EE];
__device__ float g_eval[EE];
__device__ int   g_idx64;             // 1 if rows/cols are int64, 0 if int32

// JAX silently downcasts int64->int32 when x64 is disabled; element counts
// can't disambiguate. Detect from data: int64 indices < 50000 have zero high
// words; random int32 indices at odd u32 positions are ~never all zero.
__global__ void detect_idx64_kernel(const unsigned int* __restrict__ rows_u32) {
    if (blockIdx.x == 0 && threadIdx.x == 0) {
        int is64 = 1;
        for (int i = 0; i < 64; i++) {
            if (rows_u32[2 * i + 1] != 0u) { is64 = 0; break; }
        }
        g_idx64 = is64;
    }
}

__global__ void zero_counts_kernel() {
    int i = blockIdx.x * blockDim.x + threadIdx.x;
    if (i < NN) g_fill[i] = 0;
}

__device__ __forceinline__ int load_idx(const void* p, int e) {
    return g_idx64 ? (int)reinterpret_cast<const long long*>(p)[e]
                   : reinterpret_cast<const int*>(p)[e];
}

__global__ void hist_kernel(const void* __restrict__ rows_raw) {
    int e = blockIdx.x * blockDim.x + threadIdx.x;
    if (e < EE) atomicAdd(&g_fill[load_idx(rows_raw, e)], 1);
}

// Phase 1: block-local inclusive scan of counts; per-block totals to g_bsum.
__global__ __launch_bounds__(SB)
void scan_phase1() {
    __shared__ int sh[SB];
    const int t = threadIdx.x;
    const int i = blockIdx.x * SB + t;
    int v = (i < NN) ? g_fill[i] : 0;
    sh[t] = v;
    __syncthreads();
#pragma unroll
    for (int off = 1; off < SB; off <<= 1) {
        int u = (t >= off) ? sh[t - off] : 0;
        __syncthreads();
        if (t >= off) sh[t] += u;
        __syncthreads();
    }
    if (i < NN) g_scan[i] = sh[t];
    if (t == SB - 1) g_bsum[blockIdx.x] = sh[t];
}

// Phase 2: exclusive scan of the NSB block sums (single tiny block).
__global__ __launch_bounds__(SB)
void scan_phase2() {
    __shared__ int sh[SB];
    const int t = threadIdx.x;
    sh[t] = (t < NSB) ? g_bsum[t] : 0;
    __syncthreads();
#pragma unroll
    for (int off = 1; off < SB; off <<= 1) {
        int u = (t >= off) ? sh[t - off] : 0;
        __syncthreads();
        if (t >= off) sh[t] += u;
        __syncthreads();
    }
    if (t < NSB) g_bsum[t] = (t == 0) ? 0 : sh[t - 1];   // exclusive
    if (t == 0) g_row_ptr[NN] = EE;
}

// Phase 3: row_ptr[i] = block_offset + local_inclusive - count; seed cursors.
__global__ __launch_bounds__(SB)
void scan_phase3() {
    const int i = blockIdx.x * SB + threadIdx.x;
    if (i >= NN) return;
    const int excl = g_bsum[blockIdx.x] + g_scan[i] - g_fill[i];
    g_row_ptr[i] = excl;
    g_fill[i]    = excl;   // fill cursor for permute
}

__global__ void permute_kernel(const void* __restrict__ rows_raw,
                               const void* __restrict__ cols_raw,
                               const float* __restrict__ vals) {
    int e = blockIdx.x * blockDim.x + threadIdx.x;
    if (e >= EE) return;
    int r = load_idx(rows_raw, e);
    int c = load_idx(cols_raw, e);
    int pos = atomicAdd(&g_fill[r], 1);
    g_ecol[pos] = c;
    g_eval[pos] = vals[e];
}

// One warp per node. Lane l accumulates dims {l, l+32, l+64}.
// MODE 0: src = X,    dst = bufA, out = src_row + en
// MODE 1: src = bufA, dst = bufB, out += en
// MODE 2: src = bufB, no dst,     out = (out + en) * 0.25
template<int MODE>
__global__ __launch_bounds__(256)
void layer_kernel(const float* __restrict__ X, float* __restrict__ out) {
    const int node = (blockIdx.x * blockDim.x + threadIdx.x) >> 5;
    const int lane = threadIdx.x & 31;
    if (node >= NN) return;

    const float* __restrict__ src =
        (MODE == 0) ? X : (MODE == 1 ? g_bufA : g_bufB);
    float* __restrict__ dst = (MODE == 0) ? g_bufA : g_bufB;

    const int start = g_row_ptr[node];
    const int end   = g_row_ptr[node + 1];

    float a0 = 0.f, a1 = 0.f, a2 = 0.f;
    for (int b = start; b < end; b += 32) {
        const int nb = end - b < 32 ? end - b : 32;
        int   ce = 0;
        float ve = 0.f;
        if (lane < nb) { ce = g_ecol[b + lane]; ve = g_eval[b + lane]; }
        for (int j = 0; j < nb; j++) {
            const int   c = __shfl_sync(0xffffffffu, ce, j);
            const float v = __shfl_sync(0xffffffffu, ve, j);
            const float* __restrict__ row = src + (size_t)c * D;
            a0 = fmaf(v, __ldg(row + lane),      a0);
            a1 = fmaf(v, __ldg(row + lane + 32), a1);
            a2 = fmaf(v, __ldg(row + lane + 64), a2);
        }
    }

    const float* __restrict__ my = src + (size_t)node * D;
    const float e0 = my[lane], e1 = my[lane + 32], e2 = my[lane + 64];
    const float n0 = fmaf(a0, e0, a0);
    const float n1 = fmaf(a1, e1, a1);
    const float n2 = fmaf(a2, e2, a2);

    const size_t o = (size_t)node * D;
    if (MODE != 2) {
        dst[o + lane] = n0; dst[o + lane + 32] = n1; dst[o + lane + 64] = n2;
    }
    float o0, o1, o2;
    if (MODE == 0) {
        o0 = e0 + n0; o1 = e1 + n1; o2 = e2 + n2;        // acc = X + ego1
    } else {
        o0 = out[o + lane] + n0;
        o1 = out[o + lane + 32] + n1;
        o2 = out[o + lane + 64] + n2;
    }
    if (MODE == 2) { o0 *= 0.25f; o1 *= 0.25f; o2 *= 0.25f; }
    out[o + lane] = o0; out[o + lane + 32] = o1; out[o + lane + 64] = o2;
}

extern "C" void kernel_launch(void* const* d_in, const int* in_sizes, int n_in,
                              void* d_out, int out_size) {
    const float* X    = (const float*)d_in[0];
    const float* vals = (const float*)d_in[1];
    const void*  rows = d_in[2];
    const void*  cols = d_in[3];
    float* out = (float*)d_out;

    (void)in_sizes; (void)n_in; (void)out_size;

    detect_idx64_kernel<<<1, 32>>>((const unsigned int*)rows);

    // CSR build (once per call; reused by all 3 layers)
    zero_counts_kernel<<<(NN + 255) / 256, 256>>>();
    hist_kernel<<<(EE + 255) / 256, 256>>>(rows);
    scan_phase1<<<NSB, SB>>>();
    scan_phase2<<<1, SB>>>();
    scan_phase3<<<NSB, SB>>>();
    permute_kernel<<<(EE + 255) / 256, 256>>>(rows, cols, vals);

    const int lgrid = (NN * 32 + 255) / 256;   // one warp per node
    layer_kernel<0><<<lgrid, 256>>>(X, out);
    layer_kernel<1><<<lgrid, 256>>>(X, out);
    layer_kernel<2><<<lgrid, 256>>>(X, out);
}